// round 11
// baseline (speedup 1.0000x reference)
#include <cuda_runtime.h>
#include <cuda_bf16.h>
#include <math.h>
#include <stdint.h>

#define BB 16
#define CC 512
#define HWD 1024

typedef __nv_bfloat16 bf16;

// Scratch (allocation-free)
__device__ bf16 gb_xnt[(size_t)BB*HWD*CC];    // groupnorm out, token-major [b][i][c]
__device__ bf16 gb_qk [(size_t)BB*HWD*1024];  // [b][i][qk-chan]; q=0..511, k=512..1023
__device__ bf16 gb_v  [(size_t)BB*CC*HWD];    // [b][c][j]
__device__ bf16 gb_a  [(size_t)BB*HWD*HWD];   // attn bf16 [b][i][j]
__device__ bf16 gb_o  [(size_t)BB*HWD*CC];    // [b][i][c]
__device__ float g_e  [(size_t)BB*HWD*HWD];   // energy fp32 [b][i][j]
__device__ bf16 gb_wqk[(size_t)1024*CC];      // concat [wq; wk]
__device__ bf16 gb_wv [(size_t)CC*CC];
__device__ bf16 gb_wp [(size_t)CC*CC];
__device__ float g_bqk[1024];                 // concat [bq; bk]

// ---------------- helpers ----------------
__device__ __forceinline__ uint32_t smem_u32(const void* p) {
    uint32_t a;
    asm("{ .reg .u64 t; cvta.to.shared.u64 t, %1; cvt.u32.u64 %0, t; }"
        : "=r"(a) : "l"(p));
    return a;
}
__device__ __forceinline__ uint32_t pk2(float a, float b) {
    __nv_bfloat162 t = __floats2bfloat162_rn(a, b);
    return *(uint32_t*)&t;
}
__device__ __forceinline__ void ldmx4(uint32_t* r, uint32_t addr) {
    asm volatile("ldmatrix.sync.aligned.m8n8.x4.shared.b16 {%0,%1,%2,%3}, [%4];"
                 : "=r"(r[0]), "=r"(r[1]), "=r"(r[2]), "=r"(r[3]) : "r"(addr));
}
__device__ __forceinline__ void mma_bf16(float* c, const uint32_t* a,
                                         uint32_t b0, uint32_t b1) {
    asm volatile(
        "mma.sync.aligned.m16n8k16.row.col.f32.bf16.bf16.f32 "
        "{%0,%1,%2,%3}, {%4,%5,%6,%7}, {%8,%9}, {%0,%1,%2,%3};"
        : "+f"(c[0]), "+f"(c[1]), "+f"(c[2]), "+f"(c[3])
        : "r"(a[0]), "r"(a[1]), "r"(a[2]), "r"(a[3]), "r"(b0), "r"(b1));
}
__device__ __forceinline__ void cp16(uint32_t dst, const void* src) {
    asm volatile("cp.async.cg.shared.global [%0], [%1], 16;"
                 :: "r"(dst), "l"(src) : "memory");
}
__device__ __forceinline__ void cp_commit() {
    asm volatile("cp.async.commit_group;" ::: "memory");
}

// ---------------- weight convert: build wqk/bqk, wv, wp ----------------
__global__ void cvtw_kernel(const float* __restrict__ wq, const float* __restrict__ wk,
                            const float* __restrict__ wv, const float* __restrict__ wp,
                            const float* __restrict__ bq, const float* __restrict__ bk,
                            bf16* wqk, bf16* ov, bf16* op, float* bqk)
{
    int i4 = (blockIdx.x * 256 + threadIdx.x) * 4;   // covers CC*CC = 256K
    float4 a = *(const float4*)(wq + i4);
    float4 b = *(const float4*)(wk + i4);
    float4 c = *(const float4*)(wv + i4);
    float4 d = *(const float4*)(wp + i4);
    uint2 u;
    u.x = pk2(a.x, a.y); u.y = pk2(a.z, a.w); *(uint2*)(wqk + i4) = u;
    u.x = pk2(b.x, b.y); u.y = pk2(b.z, b.w); *(uint2*)(wqk + (size_t)CC*CC + i4) = u;
    u.x = pk2(c.x, c.y); u.y = pk2(c.z, c.w); *(uint2*)(ov + i4) = u;
    u.x = pk2(d.x, d.y); u.y = pk2(d.z, d.w); *(uint2*)(op + i4) = u;
    int t = blockIdx.x * 256 + threadIdx.x;
    if (t < CC) { bqk[t] = bq[t]; bqk[t + CC] = bk[t]; }
}

// ---------------- GroupNorm + transpose -> bf16 [b][hw][c] ----------------
__global__ void groupnorm_t_kernel(const float* __restrict__ x,
                                   const float* __restrict__ gamma,
                                   const float* __restrict__ beta,
                                   bf16* __restrict__ out_t)
{
    int grp = blockIdx.x;            // b*32 + g
    int b = grp >> 5, g = grp & 31;
    const int n = 16 * HWD;
    const float* xp = x + (size_t)grp * n;
    int tid = threadIdx.x;

    float s = 0.f, ss = 0.f;
    for (int i = tid; i < n; i += 256) {
        float v = xp[i];
        s += v; ss += v * v;
    }
    __shared__ float rs[256], rss[256];
    rs[tid] = s; rss[tid] = ss;
    __syncthreads();
    for (int off = 128; off > 0; off >>= 1) {
        if (tid < off) { rs[tid] += rs[tid + off]; rss[tid] += rss[tid + off]; }
        __syncthreads();
    }
    float mean = rs[0] / n;
    float var  = rss[0] / n - mean * mean;
    float inv  = rsqrtf(var + 1e-6f);

    __shared__ float T[16][68];
    int c  = tid >> 4;
    int hl = (tid & 15) * 4;
    float gmul = gamma[g * 16 + c] * inv;
    float badd = beta[g * 16 + c] - mean * gmul;
    int hl2 = tid >> 2;
    int c2  = (tid & 3) * 4;
    bf16* orow_base = out_t + ((size_t)b * HWD) * CC + g * 16 + c2;
    __syncthreads();

    for (int hw0 = 0; hw0 < HWD; hw0 += 64) {
        float4 v = *(const float4*)&xp[c * HWD + hw0 + hl];
        T[c][hl + 0] = v.x * gmul + badd;
        T[c][hl + 1] = v.y * gmul + badd;
        T[c][hl + 2] = v.z * gmul + badd;
        T[c][hl + 3] = v.w * gmul + badd;
        __syncthreads();
        uint2 pv;
        pv.x = pk2(T[c2 + 0][hl2], T[c2 + 1][hl2]);
        pv.y = pk2(T[c2 + 2][hl2], T[c2 + 3][hl2]);
        *(uint2*)&orow_base[(size_t)(hw0 + hl2) * CC] = pv;
        __syncthreads();
    }
}

// ---------------- Row softmax: e fp32 -> attn bf16 ----------------
__global__ void softmax_kernel(const float* __restrict__ e, bf16* __restrict__ a)
{
    const float4* r4 = (const float4*)(e + (size_t)blockIdx.x * HWD);
    int t = threadIdx.x;
    float4 v = r4[t];
    float m = fmaxf(fmaxf(v.x, v.y), fmaxf(v.z, v.w));
    __shared__ float red[256];
    red[t] = m; __syncthreads();
    for (int off = 128; off > 0; off >>= 1) {
        if (t < off) red[t] = fmaxf(red[t], red[t + off]);
        __syncthreads();
    }
    m = red[0];
    __syncthreads();
    v.x = __expf(v.x - m); v.y = __expf(v.y - m);
    v.z = __expf(v.z - m); v.w = __expf(v.w - m);
    float s = v.x + v.y + v.z + v.w;
    red[t] = s; __syncthreads();
    for (int off = 128; off > 0; off >>= 1) {
        if (t < off) red[t] += red[t + off];
        __syncthreads();
    }
    float invs = 1.f / red[0];
    uint2 o;
    o.x = pk2(v.x * invs, v.y * invs);
    o.y = pk2(v.z * invs, v.w * invs);
    *(uint2*)&a[(size_t)blockIdx.x * HWD + t * 4] = o;
}

// ---------------- bf16 mma.sync GEMM: 128x128 tile, BK=64, 3-stage ----------
// C[m][n] = alpha * sum_k A[m*lda+k]*B[n*ldb+k] (+bias) (+res)
// 8 warps of 64x32, 144B-padded smem rows, 2 CTAs/SM, 1 barrier per 64 K.
// BIASMODE: 0 none, 1 per-row(m), 2 per-col(n). RES: fp32 += res. OUTF32: C dtype.

#define ROWB 144
#define TILEB (128 * ROWB)     // 18432
#define STG   (2 * TILEB)      // 36864
#define GSM   (3 * STG + 512)  // 111104

template<int BIASMODE, bool RES, bool OUTF32>
__global__ void __launch_bounds__(256, 2)
bf_gemm(const bf16* __restrict__ A, const bf16* __restrict__ B,
        void* __restrict__ Cv, const float* __restrict__ bias,
        const float* __restrict__ res,
        int K, int lda, int ldb, int ldc,
        long long sA, long long sB, long long sC, float alpha)
{
    extern __shared__ __align__(16) uint8_t sm[];
    uint32_t sb = smem_u32(sm);
    int tid = threadIdx.x, lane = tid & 31, wid = tid >> 5;
    uint32_t wm = (uint32_t)(wid >> 2) * 64;   // 0,64
    uint32_t wn = (uint32_t)(wid & 3) * 32;    // 0,32,64,96
    long long z = blockIdx.z;
    int bm0 = blockIdx.y * 128, bn0 = blockIdx.x * 128;
    const bf16* Ap = A + z * sA + (size_t)bm0 * lda;
    const bf16* Bp = B + z * sB + (size_t)bn0 * ldb;

    float* bnCol = (float*)(sm + 3 * STG);
    if (BIASMODE == 2 && tid < 128) bnCol[tid] = bias[bn0 + tid];

    // loader: row = tid>>1, 64B half each (BK=64 -> 128B per row per stage)
    const char* gA = (const char*)(Ap + (size_t)(tid >> 1) * lda) + (tid & 1) * 64;
    const char* gB = (const char*)(Bp + (size_t)(tid >> 1) * ldb) + (tid & 1) * 64;
    uint32_t sAr = sb + (uint32_t)(tid >> 1) * ROWB + (tid & 1) * 64;
    uint32_t sBr = sb + TILEB + (uint32_t)(tid >> 1) * ROWB + (tid & 1) * 64;

    int NC = K >> 6;     // 64 K per stage

    // prologue: fill stages 0,1
    #pragma unroll
    for (int s = 0; s < 2; s++) {
        #pragma unroll
        for (int u = 0; u < 4; u++) {
            cp16(sAr + s * STG + u * 16, gA + s * 128 + u * 16);
            cp16(sBr + s * STG + u * 16, gB + s * 128 + u * 16);
        }
        cp_commit();
    }

    uint32_t aoffL = (lane & 15) * ROWB + (lane >> 4) * 16;
    uint32_t boffL = ((lane & 7) + (lane >> 4) * 8) * ROWB + ((lane >> 3) & 1) * 16;

    float acc[4][4][4] = {};

    for (int i = 0; i < NC; i++) {
        if (i + 2 < NC) asm volatile("cp.async.wait_group 1;" ::: "memory");
        else            asm volatile("cp.async.wait_group 0;" ::: "memory");
        __syncthreads();

        // prefetch stage i+2 into slot (i+2)%3 (freed: computed at iter i-1)
        if (i + 2 < NC) {
            uint32_t so = (uint32_t)((i + 2) % 3) * STG;
            #pragma unroll
            for (int u = 0; u < 4; u++) {
                cp16(sAr + so + u * 16, gA + (i + 2) * 128 + u * 16);
                cp16(sBr + so + u * 16, gB + (i + 2) * 128 + u * 16);
            }
            cp_commit();
        }

        uint32_t st = sb + (uint32_t)(i % 3) * STG;
        uint32_t aT = st + wm * ROWB + aoffL;
        uint32_t bT = st + TILEB + wn * ROWB + boffL;

        #pragma unroll
        for (int ks = 0; ks < 4; ks++) {
            uint32_t af[4][4], bfr[2][4];
            #pragma unroll
            for (int mt = 0; mt < 4; mt++)
                ldmx4(af[mt], aT + mt * (16 * ROWB) + ks * 32);
            #pragma unroll
            for (int np = 0; np < 2; np++)
                ldmx4(bfr[np], bT + np * (16 * ROWB) + ks * 32);
            #pragma unroll
            for (int mt = 0; mt < 4; mt++)
                #pragma unroll
                for (int nt = 0; nt < 4; nt++)
                    mma_bf16(acc[mt][nt], af[mt],
                             bfr[nt >> 1][(nt & 1) * 2], bfr[nt >> 1][(nt & 1) * 2 + 1]);
        }
    }

    // Epilogue
    int g = lane >> 2, c = lane & 3;
    #pragma unroll
    for (int mt = 0; mt < 4; mt++) {
        int m0 = bm0 + (int)wm + mt * 16 + g;
        int m1 = m0 + 8;
        float bm_ = (BIASMODE == 1) ? bias[m0] : 0.f;
        float bm1 = (BIASMODE == 1) ? bias[m1] : 0.f;
        #pragma unroll
        for (int nt = 0; nt < 4; nt++) {
            int n = bn0 + (int)wn + nt * 8 + c * 2;
            float o0x = alpha * acc[mt][nt][0];
            float o0y = alpha * acc[mt][nt][1];
            float o1x = alpha * acc[mt][nt][2];
            float o1y = alpha * acc[mt][nt][3];
            if (BIASMODE == 1) { o0x += bm_; o0y += bm_; o1x += bm1; o1y += bm1; }
            if (BIASMODE == 2) {
                float b0 = bnCol[n - bn0], b1 = bnCol[n - bn0 + 1];
                o0x += b0; o0y += b1; o1x += b0; o1y += b1;
            }
            if (OUTF32) {
                float* Cz = (float*)Cv + z * sC;
                if (RES) {
                    const float* Rz = res + z * sC;
                    float2 r0 = *(const float2*)&Rz[(size_t)m0 * ldc + n];
                    float2 r1 = *(const float2*)&Rz[(size_t)m1 * ldc + n];
                    o0x += r0.x; o0y += r0.y; o1x += r1.x; o1y += r1.y;
                }
                float2 w0 = {o0x, o0y}, w1 = {o1x, o1y};
                *(float2*)&Cz[(size_t)m0 * ldc + n] = w0;
                *(float2*)&Cz[(size_t)m1 * ldc + n] = w1;
            } else {
                bf16* Cz = (bf16*)Cv + z * sC;
                *(uint32_t*)&Cz[(size_t)m0 * ldc + n] = pk2(o0x, o0y);
                *(uint32_t*)&Cz[(size_t)m1 * ldc + n] = pk2(o1x, o1y);
            }
        }
    }
}

extern "C" void kernel_launch(void* const* d_in, const int* in_sizes, int n_in,
                              void* d_out, int out_size)
{
    const float* x     = (const float*)d_in[0];
    const float* gamma = (const float*)d_in[1];
    const float* beta  = (const float*)d_in[2];
    const float* wq    = (const float*)d_in[3];
    const float* bq    = (const float*)d_in[4];
    const float* wk    = (const float*)d_in[5];
    const float* bk    = (const float*)d_in[6];
    const float* wv    = (const float*)d_in[7];
    const float* bv    = (const float*)d_in[8];
    const float* wp    = (const float*)d_in[9];
    const float* bp    = (const float*)d_in[10];
    float* out = (float*)d_out;

    bf16 *xnt, *qkb, *vb, *ab, *ob, *wqkb, *wvb, *wpb;
    float *e, *bqk;
    cudaGetSymbolAddress((void**)&xnt,  gb_xnt);
    cudaGetSymbolAddress((void**)&qkb,  gb_qk);
    cudaGetSymbolAddress((void**)&vb,   gb_v);
    cudaGetSymbolAddress((void**)&ab,   gb_a);
    cudaGetSymbolAddress((void**)&ob,   gb_o);
    cudaGetSymbolAddress((void**)&e,    g_e);
    cudaGetSymbolAddress((void**)&wqkb, gb_wqk);
    cudaGetSymbolAddress((void**)&wvb,  gb_wv);
    cudaGetSymbolAddress((void**)&wpb,  gb_wp);
    cudaGetSymbolAddress((void**)&bqk,  g_bqk);

    cudaFuncSetAttribute(bf_gemm<2, false, false>, cudaFuncAttributeMaxDynamicSharedMemorySize, GSM);
    cudaFuncSetAttribute(bf_gemm<1, false, false>, cudaFuncAttributeMaxDynamicSharedMemorySize, GSM);
    cudaFuncSetAttribute(bf_gemm<0, false, true>,  cudaFuncAttributeMaxDynamicSharedMemorySize, GSM);
    cudaFuncSetAttribute(bf_gemm<0, false, false>, cudaFuncAttributeMaxDynamicSharedMemorySize, GSM);
    cudaFuncSetAttribute(bf_gemm<1, true, true>,   cudaFuncAttributeMaxDynamicSharedMemorySize, GSM);

    const long long sX  = (long long)CC * HWD;    // 512K elts
    const long long sQK = (long long)HWD * 1024;  // 1M elts
    const long long sE  = (long long)HWD * HWD;   // 1M elts
    const float scale = 0.044194173824159216f;    // 512^-0.5

    // 0) weights -> bf16 (+ concat wqk/bqk)
    cvtw_kernel<<<256, 256>>>(wq, wk, wv, wp, bq, bk, wqkb, wvb, wpb, bqk);

    // 1) GroupNorm + transpose -> xnt bf16 [b][i][c]
    groupnorm_t_kernel<<<BB * 32, 256>>>(x, gamma, beta, xnt);

    // 2) QK[i][n] = sum_k xnt[i][k]*wqk[n][k] + bqk[n]   (M=1024, N=1024, K=512)
    {
        dim3 g(1024 / 128, HWD / 128, BB);
        bf_gemm<2, false, false><<<g, 256, GSM>>>(xnt, wqkb, qkb, bqk, nullptr,
            CC, CC, CC, 1024, sX, 0, sQK, 1.f);
    }
    // 3) V[c][j] = sum_k wv[c][k]*xnt[j][k] + bv[c]      (M=512, N=1024, K=512)
    {
        dim3 g(HWD / 128, CC / 128, BB);
        bf_gemm<1, false, false><<<g, 256, GSM>>>(wvb, xnt, vb, bv, nullptr,
            CC, CC, CC, HWD, 0, sX, sX, 1.f);
    }
    // 4) E[i][j] = scale * sum_c Q[i][c]*K[j][c]         (M=1024, N=1024, K=512)
    {
        dim3 g(HWD / 128, HWD / 128, BB);
        bf_gemm<0, false, true><<<g, 256, GSM>>>(qkb, qkb + CC, e, nullptr, nullptr,
            CC, 1024, 1024, HWD, sQK, sQK, sE, scale);
    }
    // 5) softmax rows of E -> attn bf16
    softmax_kernel<<<BB * HWD, 256>>>(e, ab);

    // 6) O[i][c] = sum_j attn[i][j]*V[c][j]              (M=1024, N=512, K=1024)
    {
        dim3 g(CC / 128, HWD / 128, BB);
        bf_gemm<0, false, false><<<g, 256, GSM>>>(ab, vb, ob, nullptr, nullptr,
            HWD, HWD, HWD, CC, sE, sX, sX, 1.f);
    }
    // 7) out[c][i] = sum_k wp[c][k]*O[i][k] + bp[c] + x[c][i]  (M=512, N=1024, K=512)
    {
        dim3 g(HWD / 128, CC / 128, BB);
        bf_gemm<1, true, true><<<g, 256, GSM>>>(wpb, ob, out, bp, x,
            CC, CC, CC, HWD, 0, sX, sX, 1.f);
    }
}

// round 13
// speedup vs baseline: 1.1676x; 1.1676x over previous
#include <cuda_runtime.h>
#include <cuda_bf16.h>
#include <math.h>
#include <stdint.h>

#define BB 16
#define CC 512
#define HWD 1024

typedef __nv_bfloat16 bf16;

// Scratch (allocation-free)
__device__ bf16 gb_xnt[(size_t)BB*HWD*CC];    // groupnorm out, token-major [b][i][c]
__device__ bf16 gb_qk [(size_t)BB*HWD*1024];  // [b][i][n]; q=0..511, k=512..1023
__device__ bf16 gb_v  [(size_t)BB*CC*HWD];    // [b][c][j]
__device__ bf16 gb_a  [(size_t)BB*HWD*HWD];   // attn bf16 [b][i][j]
__device__ bf16 gb_o  [(size_t)BB*HWD*CC];    // [b][i][c]
__device__ float g_e  [(size_t)BB*HWD*HWD];   // energy fp32 [b][i][j]
__device__ bf16 gb_wqk[(size_t)1024*CC];      // concat [wq; wk]
__device__ bf16 gb_wv [(size_t)CC*CC];
__device__ bf16 gb_wp [(size_t)CC*CC];
__device__ float g_bqk[1024];                 // concat [bq; bk]

// ---------------- helpers ----------------
__device__ __forceinline__ uint32_t smem_u32(const void* p) {
    uint32_t a;
    asm("{ .reg .u64 t; cvta.to.shared.u64 t, %1; cvt.u32.u64 %0, t; }"
        : "=r"(a) : "l"(p));
    return a;
}
__device__ __forceinline__ uint32_t pk2(float a, float b) {
    __nv_bfloat162 t = __floats2bfloat162_rn(a, b);
    return *(uint32_t*)&t;
}
__device__ __forceinline__ void ldmx4(uint32_t* r, uint32_t addr) {
    asm volatile("ldmatrix.sync.aligned.m8n8.x4.shared.b16 {%0,%1,%2,%3}, [%4];"
                 : "=r"(r[0]), "=r"(r[1]), "=r"(r[2]), "=r"(r[3]) : "r"(addr));
}
__device__ __forceinline__ void mma_bf16(float* c, const uint32_t* a,
                                         uint32_t b0, uint32_t b1) {
    asm volatile(
        "mma.sync.aligned.m16n8k16.row.col.f32.bf16.bf16.f32 "
        "{%0,%1,%2,%3}, {%4,%5,%6,%7}, {%8,%9}, {%0,%1,%2,%3};"
        : "+f"(c[0]), "+f"(c[1]), "+f"(c[2]), "+f"(c[3])
        : "r"(a[0]), "r"(a[1]), "r"(a[2]), "r"(a[3]), "r"(b0), "r"(b1));
}
__device__ __forceinline__ void cp16(uint32_t dst, const void* src) {
    asm volatile("cp.async.cg.shared.global [%0], [%1], 16;"
                 :: "r"(dst), "l"(src) : "memory");
}
__device__ __forceinline__ void cp_commit() {
    asm volatile("cp.async.commit_group;" ::: "memory");
}

// ---------------- weight convert: build wqk/bqk, wv, wp ----------------
__global__ void cvtw_kernel(const float* __restrict__ wq, const float* __restrict__ wk,
                            const float* __restrict__ wv, const float* __restrict__ wp,
                            const float* __restrict__ bq, const float* __restrict__ bk,
                            bf16* wqk, bf16* ov, bf16* op, float* bqk)
{
    int i4 = (blockIdx.x * 256 + threadIdx.x) * 4;   // covers CC*CC = 256K
    float4 a = *(const float4*)(wq + i4);
    float4 b = *(const float4*)(wk + i4);
    float4 c = *(const float4*)(wv + i4);
    float4 d = *(const float4*)(wp + i4);
    uint2 u;
    u.x = pk2(a.x, a.y); u.y = pk2(a.z, a.w); *(uint2*)(wqk + i4) = u;
    u.x = pk2(b.x, b.y); u.y = pk2(b.z, b.w); *(uint2*)(wqk + (size_t)CC*CC + i4) = u;
    u.x = pk2(c.x, c.y); u.y = pk2(c.z, c.w); *(uint2*)(ov + i4) = u;
    u.x = pk2(d.x, d.y); u.y = pk2(d.z, d.w); *(uint2*)(op + i4) = u;
    int t = blockIdx.x * 256 + threadIdx.x;
    if (t < CC) { bqk[t] = bq[t]; bqk[t + CC] = bk[t]; }
}

// ---------------- GroupNorm + transpose -> bf16 [b][hw][c] ----------------
__global__ void groupnorm_t_kernel(const float* __restrict__ x,
                                   const float* __restrict__ gamma,
                                   const float* __restrict__ beta,
                                   bf16* __restrict__ out_t)
{
    int grp = blockIdx.x;            // b*32 + g
    int b = grp >> 5, g = grp & 31;
    const int n = 16 * HWD;
    const float* xp = x + (size_t)grp * n;
    int tid = threadIdx.x;

    float s = 0.f, ss = 0.f;
    for (int i = tid; i < n; i += 256) {
        float v = xp[i];
        s += v; ss += v * v;
    }
    __shared__ float rs[256], rss[256];
    rs[tid] = s; rss[tid] = ss;
    __syncthreads();
    for (int off = 128; off > 0; off >>= 1) {
        if (tid < off) { rs[tid] += rs[tid + off]; rss[tid] += rss[tid + off]; }
        __syncthreads();
    }
    float mean = rs[0] / n;
    float var  = rss[0] / n - mean * mean;
    float inv  = rsqrtf(var + 1e-6f);

    __shared__ float T[16][68];
    int c  = tid >> 4;
    int hl = (tid & 15) * 4;
    float gmul = gamma[g * 16 + c] * inv;
    float badd = beta[g * 16 + c] - mean * gmul;
    int hl2 = tid >> 2;
    int c2  = (tid & 3) * 4;
    bf16* orow_base = out_t + ((size_t)b * HWD) * CC + g * 16 + c2;
    __syncthreads();

    for (int hw0 = 0; hw0 < HWD; hw0 += 64) {
        float4 v = *(const float4*)&xp[c * HWD + hw0 + hl];
        T[c][hl + 0] = v.x * gmul + badd;
        T[c][hl + 1] = v.y * gmul + badd;
        T[c][hl + 2] = v.z * gmul + badd;
        T[c][hl + 3] = v.w * gmul + badd;
        __syncthreads();
        uint2 pv;
        pv.x = pk2(T[c2 + 0][hl2], T[c2 + 1][hl2]);
        pv.y = pk2(T[c2 + 2][hl2], T[c2 + 3][hl2]);
        *(uint2*)&orow_base[(size_t)(hw0 + hl2) * CC] = pv;
        __syncthreads();
    }
}

// ---------------- Row softmax: e fp32 -> attn bf16 ----------------
__global__ void softmax_kernel(const float* __restrict__ e, bf16* __restrict__ a)
{
    const float4* r4 = (const float4*)(e + (size_t)blockIdx.x * HWD);
    int t = threadIdx.x;
    float4 v = r4[t];
    float m = fmaxf(fmaxf(v.x, v.y), fmaxf(v.z, v.w));
    __shared__ float red[256];
    red[t] = m; __syncthreads();
    for (int off = 128; off > 0; off >>= 1) {
        if (t < off) red[t] = fmaxf(red[t], red[t + off]);
        __syncthreads();
    }
    m = red[0];
    __syncthreads();
    v.x = __expf(v.x - m); v.y = __expf(v.y - m);
    v.z = __expf(v.z - m); v.w = __expf(v.w - m);
    float s = v.x + v.y + v.z + v.w;
    red[t] = s; __syncthreads();
    for (int off = 128; off > 0; off >>= 1) {
        if (t < off) red[t] += red[t + off];
        __syncthreads();
    }
    float invs = 1.f / red[0];
    uint2 o;
    o.x = pk2(v.x * invs, v.y * invs);
    o.y = pk2(v.z * invs, v.w * invs);
    *(uint2*)&a[(size_t)blockIdx.x * HWD + t * 4] = o;
}

// ---------------- bf16 mma.sync GEMM: 128x128 tile, 8 warps of 64x32 --------
// (Round-10 proven config: BK=32, 4-stage cp.async ring, 2 CTAs/SM)
// C[m][n] = alpha * sum_k A[m*lda+k]*B[n*ldb+k] (+bias) (+res)
// BIASMODE: 0 none, 1 per-row(m), 2 per-col(n). RES: fp32 += res. OUTF32: C dtype.

#define ROWB 80
#define TILEB (128 * ROWB)     // 10240
#define STG   (2 * TILEB)      // 20480
#define GSM   (4 * STG + 512)  // 82432

template<int BIASMODE, bool RES, bool OUTF32>
__global__ void __launch_bounds__(256, 2)
bf_gemm(const bf16* __restrict__ A, const bf16* __restrict__ B,
        void* __restrict__ Cv, const float* __restrict__ bias,
        const float* __restrict__ res,
        int K, int lda, int ldb, int ldc,
        long long sA, long long sB, long long sC, float alpha)
{
    extern __shared__ __align__(16) uint8_t sm[];
    uint32_t sb = smem_u32(sm);
    int tid = threadIdx.x, lane = tid & 31, wid = tid >> 5;
    uint32_t wm = (uint32_t)(wid >> 2) * 64;   // 0,64
    uint32_t wn = (uint32_t)(wid & 3) * 32;    // 0,32,64,96
    long long z = blockIdx.z;
    int bm0 = blockIdx.y * 128, bn0 = blockIdx.x * 128;
    const bf16* Ap = A + z * sA + (size_t)bm0 * lda;
    const bf16* Bp = B + z * sB + (size_t)bn0 * ldb;

    float* bnCol = (float*)(sm + 4 * STG);
    if (BIASMODE == 2 && tid < 128) bnCol[tid] = bias[bn0 + tid];

    // loader: row = tid>>1 of both tiles, 32B half each
    const char* gA = (const char*)(Ap + (size_t)(tid >> 1) * lda) + (tid & 1) * 32;
    const char* gB = (const char*)(Bp + (size_t)(tid >> 1) * ldb) + (tid & 1) * 32;
    uint32_t sAr = sb + (uint32_t)(tid >> 1) * ROWB + (tid & 1) * 32;
    uint32_t sBr = sb + TILEB + (uint32_t)(tid >> 1) * ROWB + (tid & 1) * 32;

    int NC = K >> 5;

    // prologue: fill stages 0..2
    #pragma unroll
    for (int s = 0; s < 3; s++) {
        cp16(sAr + s * STG,      gA + s * 64);
        cp16(sAr + s * STG + 16, gA + s * 64 + 16);
        cp16(sBr + s * STG,      gB + s * 64);
        cp16(sBr + s * STG + 16, gB + s * 64 + 16);
        cp_commit();
    }

    uint32_t aoffL = (lane & 15) * ROWB + (lane >> 4) * 16;
    uint32_t boffL = ((lane & 7) + (lane >> 4) * 8) * ROWB + ((lane >> 3) & 1) * 16;

    float acc[4][4][4] = {};

    for (int i = 0; i < NC; i++) {
        if (i + 3 < NC) asm volatile("cp.async.wait_group 2;" ::: "memory");
        else            asm volatile("cp.async.wait_group 0;" ::: "memory");
        __syncthreads();

        uint32_t st = sb + (uint32_t)(i & 3) * STG;
        uint32_t aT = st + wm * ROWB + aoffL;
        uint32_t bT = st + TILEB + wn * ROWB + boffL;

        // ks = 0
        {
            uint32_t af[4][4], bfr[2][4];
            #pragma unroll
            for (int mt = 0; mt < 4; mt++) ldmx4(af[mt], aT + mt * (16 * ROWB));
            #pragma unroll
            for (int np = 0; np < 2; np++) ldmx4(bfr[np], bT + np * (16 * ROWB));
            #pragma unroll
            for (int mt = 0; mt < 4; mt++)
                #pragma unroll
                for (int nt = 0; nt < 4; nt++)
                    mma_bf16(acc[mt][nt], af[mt],
                             bfr[nt >> 1][(nt & 1) * 2], bfr[nt >> 1][(nt & 1) * 2 + 1]);
        }

        // feed stage i+3 (ring slot (i-1)&3; safe: bar above proved reads done)
        if (i + 3 < NC) {
            uint32_t so = (uint32_t)((i + 3) & 3) * STG;
            cp16(sAr + so,      gA + (i + 3) * 64);
            cp16(sAr + so + 16, gA + (i + 3) * 64 + 16);
            cp16(sBr + so,      gB + (i + 3) * 64);
            cp16(sBr + so + 16, gB + (i + 3) * 64 + 16);
            cp_commit();
        }

        // ks = 1
        {
            uint32_t af[4][4], bfr[2][4];
            #pragma unroll
            for (int mt = 0; mt < 4; mt++) ldmx4(af[mt], aT + mt * (16 * ROWB) + 32);
            #pragma unroll
            for (int np = 0; np < 2; np++) ldmx4(bfr[np], bT + np * (16 * ROWB) + 32);
            #pragma unroll
            for (int mt = 0; mt < 4; mt++)
                #pragma unroll
                for (int nt = 0; nt < 4; nt++)
                    mma_bf16(acc[mt][nt], af[mt],
                             bfr[nt >> 1][(nt & 1) * 2], bfr[nt >> 1][(nt & 1) * 2 + 1]);
        }
    }

    // Epilogue
    int g = lane >> 2, c = lane & 3;
    #pragma unroll
    for (int mt = 0; mt < 4; mt++) {
        int m0 = bm0 + (int)wm + mt * 16 + g;
        int m1 = m0 + 8;
        float bm_ = (BIASMODE == 1) ? bias[m0] : 0.f;
        float bm1 = (BIASMODE == 1) ? bias[m1] : 0.f;
        #pragma unroll
        for (int nt = 0; nt < 4; nt++) {
            int n = bn0 + (int)wn + nt * 8 + c * 2;
            float o0x = alpha * acc[mt][nt][0];
            float o0y = alpha * acc[mt][nt][1];
            float o1x = alpha * acc[mt][nt][2];
            float o1y = alpha * acc[mt][nt][3];
            if (BIASMODE == 1) { o0x += bm_; o0y += bm_; o1x += bm1; o1y += bm1; }
            if (BIASMODE == 2) {
                float b0 = bnCol[n - bn0], b1 = bnCol[n - bn0 + 1];
                o0x += b0; o0y += b1; o1x += b0; o1y += b1;
            }
            if (OUTF32) {
                float* Cz = (float*)Cv + z * sC;
                if (RES) {
                    const float* Rz = res + z * sC;
                    float2 r0 = *(const float2*)&Rz[(size_t)m0 * ldc + n];
                    float2 r1 = *(const float2*)&Rz[(size_t)m1 * ldc + n];
                    o0x += r0.x; o0y += r0.y; o1x += r1.x; o1y += r1.y;
                }
                float2 w0 = {o0x, o0y}, w1 = {o1x, o1y};
                *(float2*)&Cz[(size_t)m0 * ldc + n] = w0;
                *(float2*)&Cz[(size_t)m1 * ldc + n] = w1;
            } else {
                bf16* Cz = (bf16*)Cv + z * sC;
                *(uint32_t*)&Cz[(size_t)m0 * ldc + n] = pk2(o0x, o0y);
                *(uint32_t*)&Cz[(size_t)m1 * ldc + n] = pk2(o1x, o1y);
            }
        }
    }
}

extern "C" void kernel_launch(void* const* d_in, const int* in_sizes, int n_in,
                              void* d_out, int out_size)
{
    const float* x     = (const float*)d_in[0];
    const float* gamma = (const float*)d_in[1];
    const float* beta  = (const float*)d_in[2];
    const float* wq    = (const float*)d_in[3];
    const float* bq    = (const float*)d_in[4];
    const float* wk    = (const float*)d_in[5];
    const float* bk    = (const float*)d_in[6];
    const float* wv    = (const float*)d_in[7];
    const float* bv    = (const float*)d_in[8];
    const float* wp    = (const float*)d_in[9];
    const float* bp    = (const float*)d_in[10];
    float* out = (float*)d_out;

    bf16 *xnt, *qkb, *vb, *ab, *ob, *wqkb, *wvb, *wpb;
    float *e, *bqk;
    cudaGetSymbolAddress((void**)&xnt,  gb_xnt);
    cudaGetSymbolAddress((void**)&qkb,  gb_qk);
    cudaGetSymbolAddress((void**)&vb,   gb_v);
    cudaGetSymbolAddress((void**)&ab,   gb_a);
    cudaGetSymbolAddress((void**)&ob,   gb_o);
    cudaGetSymbolAddress((void**)&e,    g_e);
    cudaGetSymbolAddress((void**)&wqkb, gb_wqk);
    cudaGetSymbolAddress((void**)&wvb,  gb_wv);
    cudaGetSymbolAddress((void**)&wpb,  gb_wp);
    cudaGetSymbolAddress((void**)&bqk,  g_bqk);

    cudaFuncSetAttribute(bf_gemm<2, false, false>, cudaFuncAttributeMaxDynamicSharedMemorySize, GSM);
    cudaFuncSetAttribute(bf_gemm<1, false, false>, cudaFuncAttributeMaxDynamicSharedMemorySize, GSM);
    cudaFuncSetAttribute(bf_gemm<0, false, true>,  cudaFuncAttributeMaxDynamicSharedMemorySize, GSM);
    cudaFuncSetAttribute(bf_gemm<0, false, false>, cudaFuncAttributeMaxDynamicSharedMemorySize, GSM);
    cudaFuncSetAttribute(bf_gemm<1, true, true>,   cudaFuncAttributeMaxDynamicSharedMemorySize, GSM);

    const long long sX  = (long long)CC * HWD;    // 512K elts
    const long long sQK = (long long)HWD * 1024;  // 1M elts
    const long long sE  = (long long)HWD * HWD;   // 1M elts
    const float scale = 0.044194173824159216f;    // 512^-0.5

    // 0) weights -> bf16 (+ concat wqk/bqk)
    cvtw_kernel<<<256, 256>>>(wq, wk, wv, wp, bq, bk, wqkb, wvb, wpb, bqk);

    // 1) GroupNorm + transpose -> xnt bf16 [b][i][c]
    groupnorm_t_kernel<<<BB * 32, 256>>>(x, gamma, beta, xnt);

    // 2) QK[i][n] = sum_k xnt[i][k]*wqk[n][k] + bqk[n]   (M=1024, N=1024, K=512)
    {
        dim3 g(1024 / 128, HWD / 128, BB);
        bf_gemm<2, false, false><<<g, 256, GSM>>>(xnt, wqkb, qkb, bqk, nullptr,
            CC, CC, CC, 1024, sX, 0, sQK, 1.f);
    }
    // 3) V[c][j] = sum_k wv[c][k]*xnt[j][k] + bv[c]      (M=512, N=1024, K=512)
    {
        dim3 g(HWD / 128, CC / 128, BB);
        bf_gemm<1, false, false><<<g, 256, GSM>>>(wvb, xnt, vb, bv, nullptr,
            CC, CC, CC, HWD, 0, sX, sX, 1.f);
    }
    // 4) E[i][j] = scale * sum_c Q[i][c]*K[j][c]         (M=1024, N=1024, K=512)
    {
        dim3 g(HWD / 128, HWD / 128, BB);
        bf_gemm<0, false, true><<<g, 256, GSM>>>(qkb, qkb + CC, e, nullptr, nullptr,
            CC, 1024, 1024, HWD, sQK, sQK, sE, scale);
    }
    // 5) softmax rows of E -> attn bf16
    softmax_kernel<<<BB * HWD, 256>>>(e, ab);

    // 6) O[i][c] = sum_j attn[i][j]*V[c][j]              (M=1024, N=512, K=1024)
    {
        dim3 g(CC / 128, HWD / 128, BB);
        bf_gemm<0, false, false><<<g, 256, GSM>>>(ab, vb, ob, nullptr, nullptr,
            HWD, HWD, HWD, CC, sE, sX, sX, 1.f);
    }
    // 7) out[c][i] = sum_k wp[c][k]*O[i][k] + bp[c] + x[c][i]  (M=512, N=1024, K=512)
    {
        dim3 g(HWD / 128, CC / 128, BB);
        bf_gemm<1, true, true><<<g, 256, GSM>>>(wpb, ob, out, bp, x,
            CC, CC, CC, HWD, 0, sX, sX, 1.f);
    }
}

// round 14
// speedup vs baseline: 1.2259x; 1.0499x over previous
#include <cuda_runtime.h>
#include <cuda_bf16.h>
#include <math.h>
#include <stdint.h>

#define BB 16
#define CC 512
#define HWD 1024

typedef __nv_bfloat16 bf16;

// Scratch (allocation-free)
__device__ bf16 gb_xnt[(size_t)BB*HWD*CC];    // groupnorm out, token-major [b][i][c]
__device__ bf16 gb_qk [(size_t)BB*HWD*1024];  // [b][i][n]; q=0..511, k=512..1023
__device__ bf16 gb_v  [(size_t)BB*CC*HWD];    // [b][c][j]
__device__ bf16 gb_a  [(size_t)BB*HWD*HWD];   // attn bf16 [b][i][j]
__device__ bf16 gb_o  [(size_t)BB*HWD*CC];    // [b][i][c]
__device__ float g_e  [(size_t)BB*HWD*HWD];   // energy fp32 [b][i][j]
__device__ bf16 gb_wqk[(size_t)1024*CC];      // concat [wq; wk]
__device__ bf16 gb_wv [(size_t)CC*CC];
__device__ bf16 gb_wp [(size_t)CC*CC];
__device__ float g_bqk[1024];                 // concat [bq; bk]

// ---------------- helpers ----------------
__device__ __forceinline__ uint32_t smem_u32(const void* p) {
    uint32_t a;
    asm("{ .reg .u64 t; cvta.to.shared.u64 t, %1; cvt.u32.u64 %0, t; }"
        : "=r"(a) : "l"(p));
    return a;
}
__device__ __forceinline__ uint32_t pk2(float a, float b) {
    __nv_bfloat162 t = __floats2bfloat162_rn(a, b);
    return *(uint32_t*)&t;
}
__device__ __forceinline__ void ldmx4(uint32_t* r, uint32_t addr) {
    asm volatile("ldmatrix.sync.aligned.m8n8.x4.shared.b16 {%0,%1,%2,%3}, [%4];"
                 : "=r"(r[0]), "=r"(r[1]), "=r"(r[2]), "=r"(r[3]) : "r"(addr));
}
__device__ __forceinline__ void mma_bf16(float* c, const uint32_t* a,
                                         uint32_t b0, uint32_t b1) {
    asm volatile(
        "mma.sync.aligned.m16n8k16.row.col.f32.bf16.bf16.f32 "
        "{%0,%1,%2,%3}, {%4,%5,%6,%7}, {%8,%9}, {%0,%1,%2,%3};"
        : "+f"(c[0]), "+f"(c[1]), "+f"(c[2]), "+f"(c[3])
        : "r"(a[0]), "r"(a[1]), "r"(a[2]), "r"(a[3]), "r"(b0), "r"(b1));
}
__device__ __forceinline__ void cp16(uint32_t dst, const void* src) {
    asm volatile("cp.async.cg.shared.global [%0], [%1], 16;"
                 :: "r"(dst), "l"(src) : "memory");
}
__device__ __forceinline__ void cp_commit() {
    asm volatile("cp.async.commit_group;" ::: "memory");
}

// ---------------- weight convert: build wqk/bqk, wv, wp ----------------
__global__ void cvtw_kernel(const float* __restrict__ wq, const float* __restrict__ wk,
                            const float* __restrict__ wv, const float* __restrict__ wp,
                            const float* __restrict__ bq, const float* __restrict__ bk,
                            bf16* wqk, bf16* ov, bf16* op, float* bqk)
{
    int i4 = (blockIdx.x * 256 + threadIdx.x) * 4;   // covers CC*CC = 256K
    float4 a = *(const float4*)(wq + i4);
    float4 b = *(const float4*)(wk + i4);
    float4 c = *(const float4*)(wv + i4);
    float4 d = *(const float4*)(wp + i4);
    uint2 u;
    u.x = pk2(a.x, a.y); u.y = pk2(a.z, a.w); *(uint2*)(wqk + i4) = u;
    u.x = pk2(b.x, b.y); u.y = pk2(b.z, b.w); *(uint2*)(wqk + (size_t)CC*CC + i4) = u;
    u.x = pk2(c.x, c.y); u.y = pk2(c.z, c.w); *(uint2*)(ov + i4) = u;
    u.x = pk2(d.x, d.y); u.y = pk2(d.z, d.w); *(uint2*)(op + i4) = u;
    int t = blockIdx.x * 256 + threadIdx.x;
    if (t < CC) { bqk[t] = bq[t]; bqk[t + CC] = bk[t]; }
}

// ---------------- GroupNorm + transpose -> bf16 [b][hw][c] ----------------
__global__ void groupnorm_t_kernel(const float* __restrict__ x,
                                   const float* __restrict__ gamma,
                                   const float* __restrict__ beta,
                                   bf16* __restrict__ out_t)
{
    int grp = blockIdx.x;            // b*32 + g
    int b = grp >> 5, g = grp & 31;
    const int n = 16 * HWD;
    const float* xp = x + (size_t)grp * n;
    int tid = threadIdx.x;

    float s = 0.f, ss = 0.f;
    for (int i = tid; i < n; i += 256) {
        float v = xp[i];
        s += v; ss += v * v;
    }
    __shared__ float rs[256], rss[256];
    rs[tid] = s; rss[tid] = ss;
    __syncthreads();
    for (int off = 128; off > 0; off >>= 1) {
        if (tid < off) { rs[tid] += rs[tid + off]; rss[tid] += rss[tid + off]; }
        __syncthreads();
    }
    float mean = rs[0] / n;
    float var  = rss[0] / n - mean * mean;
    float inv  = rsqrtf(var + 1e-6f);

    __shared__ float T[16][68];
    int c  = tid >> 4;
    int hl = (tid & 15) * 4;
    float gmul = gamma[g * 16 + c] * inv;
    float badd = beta[g * 16 + c] - mean * gmul;
    int hl2 = tid >> 2;
    int c2  = (tid & 3) * 4;
    bf16* orow_base = out_t + ((size_t)b * HWD) * CC + g * 16 + c2;
    __syncthreads();

    for (int hw0 = 0; hw0 < HWD; hw0 += 64) {
        float4 v = *(const float4*)&xp[c * HWD + hw0 + hl];
        T[c][hl + 0] = v.x * gmul + badd;
        T[c][hl + 1] = v.y * gmul + badd;
        T[c][hl + 2] = v.z * gmul + badd;
        T[c][hl + 3] = v.w * gmul + badd;
        __syncthreads();
        uint2 pv;
        pv.x = pk2(T[c2 + 0][hl2], T[c2 + 1][hl2]);
        pv.y = pk2(T[c2 + 2][hl2], T[c2 + 3][hl2]);
        *(uint2*)&orow_base[(size_t)(hw0 + hl2) * CC] = pv;
        __syncthreads();
    }
}

// ---------------- Row softmax: e fp32 -> attn bf16 ----------------
__global__ void softmax_kernel(const float* __restrict__ e, bf16* __restrict__ a)
{
    const float4* r4 = (const float4*)(e + (size_t)blockIdx.x * HWD);
    int t = threadIdx.x;
    float4 v = r4[t];
    float m = fmaxf(fmaxf(v.x, v.y), fmaxf(v.z, v.w));
    __shared__ float red[256];
    red[t] = m; __syncthreads();
    for (int off = 128; off > 0; off >>= 1) {
        if (t < off) red[t] = fmaxf(red[t], red[t + off]);
        __syncthreads();
    }
    m = red[0];
    __syncthreads();
    v.x = __expf(v.x - m); v.y = __expf(v.y - m);
    v.z = __expf(v.z - m); v.w = __expf(v.w - m);
    float s = v.x + v.y + v.z + v.w;
    red[t] = s; __syncthreads();
    for (int off = 128; off > 0; off >>= 1) {
        if (t < off) red[t] += red[t + off];
        __syncthreads();
    }
    float invs = 1.f / red[0];
    uint2 o;
    o.x = pk2(v.x * invs, v.y * invs);
    o.y = pk2(v.z * invs, v.w * invs);
    *(uint2*)&a[(size_t)blockIdx.x * HWD + t * 4] = o;
}

// ---------------- bf16 mma.sync GEMM: 256x128 tile, 16 warps of 64x32 -------
// BK=32, 4-stage cp.async ring, 1 CTA/SM, 512 threads.
// C[m][n] = alpha * sum_k A[m*lda+k]*B[n*ldb+k] (+bias) (+res)
// BIASMODE: 0 none, 1 per-row(m), 2 per-col(n). RES: fp32 += res. OUTF32: C dtype.

#define ROWB 80
#define ATILEB (256 * ROWB)        // 20480
#define BTILEB (128 * ROWB)        // 10240
#define STG    (ATILEB + BTILEB)   // 30720
#define GSM    (4 * STG + 512)     // 123392

template<int BIASMODE, bool RES, bool OUTF32>
__global__ void __launch_bounds__(512, 1)
bf_gemm(const bf16* __restrict__ A, const bf16* __restrict__ B,
        void* __restrict__ Cv, const float* __restrict__ bias,
        const float* __restrict__ res,
        int K, int lda, int ldb, int ldc,
        long long sA, long long sB, long long sC, float alpha)
{
    extern __shared__ __align__(16) uint8_t sm[];
    uint32_t sb = smem_u32(sm);
    int tid = threadIdx.x, lane = tid & 31, wid = tid >> 5;
    uint32_t wm = (uint32_t)(wid >> 2) * 64;   // 0..192
    uint32_t wn = (uint32_t)(wid & 3) * 32;    // 0..96
    long long z = blockIdx.z;
    int bm0 = blockIdx.y * 256, bn0 = blockIdx.x * 128;
    const bf16* Ap = A + z * sA + (size_t)bm0 * lda;
    const bf16* Bp = B + z * sB + (size_t)bn0 * ldb;

    float* bnCol = (float*)(sm + 4 * STG);
    if (BIASMODE == 2 && tid < 128) bnCol[tid] = bias[bn0 + tid];

    // loader: A row = tid>>1 (0..255), 32B half; B row = tid>>2 (0..127), 16B quarter
    const char* gA = (const char*)(Ap + (size_t)(tid >> 1) * lda) + (tid & 1) * 32;
    const char* gB = (const char*)(Bp + (size_t)(tid >> 2) * ldb) + (tid & 3) * 16;
    uint32_t sAr = sb + (uint32_t)(tid >> 1) * ROWB + (tid & 1) * 32;
    uint32_t sBr = sb + ATILEB + (uint32_t)(tid >> 2) * ROWB + (tid & 3) * 16;

    int NC = K >> 5;

    // prologue: fill stages 0..2
    #pragma unroll
    for (int s = 0; s < 3; s++) {
        cp16(sAr + s * STG,      gA + s * 64);
        cp16(sAr + s * STG + 16, gA + s * 64 + 16);
        cp16(sBr + s * STG,      gB + s * 64);
        cp_commit();
    }

    uint32_t aoffL = (lane & 15) * ROWB + (lane >> 4) * 16;
    uint32_t boffL = ((lane & 7) + (lane >> 4) * 8) * ROWB + ((lane >> 3) & 1) * 16;

    float acc[4][4][4] = {};

    for (int i = 0; i < NC; i++) {
        if (i + 3 < NC) asm volatile("cp.async.wait_group 2;" ::: "memory");
        else            asm volatile("cp.async.wait_group 0;" ::: "memory");
        __syncthreads();

        uint32_t st = sb + (uint32_t)(i & 3) * STG;
        uint32_t aT = st + wm * ROWB + aoffL;
        uint32_t bT = st + ATILEB + wn * ROWB + boffL;

        // ks = 0
        {
            uint32_t af[4][4], bfr[2][4];
            #pragma unroll
            for (int mt = 0; mt < 4; mt++) ldmx4(af[mt], aT + mt * (16 * ROWB));
            #pragma unroll
            for (int np = 0; np < 2; np++) ldmx4(bfr[np], bT + np * (16 * ROWB));
            #pragma unroll
            for (int mt = 0; mt < 4; mt++)
                #pragma unroll
                for (int nt = 0; nt < 4; nt++)
                    mma_bf16(acc[mt][nt], af[mt],
                             bfr[nt >> 1][(nt & 1) * 2], bfr[nt >> 1][(nt & 1) * 2 + 1]);
        }

        // feed stage i+3 (slot freed by barrier above)
        if (i + 3 < NC) {
            uint32_t so = (uint32_t)((i + 3) & 3) * STG;
            cp16(sAr + so,      gA + (i + 3) * 64);
            cp16(sAr + so + 16, gA + (i + 3) * 64 + 16);
            cp16(sBr + so,      gB + (i + 3) * 64);
            cp_commit();
        }

        // ks = 1
        {
            uint32_t af[4][4], bfr[2][4];
            #pragma unroll
            for (int mt = 0; mt < 4; mt++) ldmx4(af[mt], aT + mt * (16 * ROWB) + 32);
            #pragma unroll
            for (int np = 0; np < 2; np++) ldmx4(bfr[np], bT + np * (16 * ROWB) + 32);
            #pragma unroll
            for (int mt = 0; mt < 4; mt++)
                #pragma unroll
                for (int nt = 0; nt < 4; nt++)
                    mma_bf16(acc[mt][nt], af[mt],
                             bfr[nt >> 1][(nt & 1) * 2], bfr[nt >> 1][(nt & 1) * 2 + 1]);
        }
    }

    // Epilogue
    int g = lane >> 2, c = lane & 3;
    #pragma unroll
    for (int mt = 0; mt < 4; mt++) {
        int m0 = bm0 + (int)wm + mt * 16 + g;
        int m1 = m0 + 8;
        float bm_ = (BIASMODE == 1) ? bias[m0] : 0.f;
        float bm1 = (BIASMODE == 1) ? bias[m1] : 0.f;
        #pragma unroll
        for (int nt = 0; nt < 4; nt++) {
            int n = bn0 + (int)wn + nt * 8 + c * 2;
            float o0x = alpha * acc[mt][nt][0];
            float o0y = alpha * acc[mt][nt][1];
            float o1x = alpha * acc[mt][nt][2];
            float o1y = alpha * acc[mt][nt][3];
            if (BIASMODE == 1) { o0x += bm_; o0y += bm_; o1x += bm1; o1y += bm1; }
            if (BIASMODE == 2) {
                float b0 = bnCol[n - bn0], b1 = bnCol[n - bn0 + 1];
                o0x += b0; o0y += b1; o1x += b0; o1y += b1;
            }
            if (OUTF32) {
                float* Cz = (float*)Cv + z * sC;
                if (RES) {
                    const float* Rz = res + z * sC;
                    float2 r0 = *(const float2*)&Rz[(size_t)m0 * ldc + n];
                    float2 r1 = *(const float2*)&Rz[(size_t)m1 * ldc + n];
                    o0x += r0.x; o0y += r0.y; o1x += r1.x; o1y += r1.y;
                }
                float2 w0 = {o0x, o0y}, w1 = {o1x, o1y};
                *(float2*)&Cz[(size_t)m0 * ldc + n] = w0;
                *(float2*)&Cz[(size_t)m1 * ldc + n] = w1;
            } else {
                bf16* Cz = (bf16*)Cv + z * sC;
                *(uint32_t*)&Cz[(size_t)m0 * ldc + n] = pk2(o0x, o0y);
                *(uint32_t*)&Cz[(size_t)m1 * ldc + n] = pk2(o1x, o1y);
            }
        }
    }
}

extern "C" void kernel_launch(void* const* d_in, const int* in_sizes, int n_in,
                              void* d_out, int out_size)
{
    const float* x     = (const float*)d_in[0];
    const float* gamma = (const float*)d_in[1];
    const float* beta  = (const float*)d_in[2];
    const float* wq    = (const float*)d_in[3];
    const float* bq    = (const float*)d_in[4];
    const float* wk    = (const float*)d_in[5];
    const float* bk    = (const float*)d_in[6];
    const float* wv    = (const float*)d_in[7];
    const float* bv    = (const float*)d_in[8];
    const float* wp    = (const float*)d_in[9];
    const float* bp    = (const float*)d_in[10];
    float* out = (float*)d_out;

    bf16 *xnt, *qkb, *vb, *ab, *ob, *wqkb, *wvb, *wpb;
    float *e, *bqk;
    cudaGetSymbolAddress((void**)&xnt,  gb_xnt);
    cudaGetSymbolAddress((void**)&qkb,  gb_qk);
    cudaGetSymbolAddress((void**)&vb,   gb_v);
    cudaGetSymbolAddress((void**)&ab,   gb_a);
    cudaGetSymbolAddress((void**)&ob,   gb_o);
    cudaGetSymbolAddress((void**)&e,    g_e);
    cudaGetSymbolAddress((void**)&wqkb, gb_wqk);
    cudaGetSymbolAddress((void**)&wvb,  gb_wv);
    cudaGetSymbolAddress((void**)&wpb,  gb_wp);
    cudaGetSymbolAddress((void**)&bqk,  g_bqk);

    cudaFuncSetAttribute(bf_gemm<2, false, false>, cudaFuncAttributeMaxDynamicSharedMemorySize, GSM);
    cudaFuncSetAttribute(bf_gemm<1, false, false>, cudaFuncAttributeMaxDynamicSharedMemorySize, GSM);
    cudaFuncSetAttribute(bf_gemm<0, false, true>,  cudaFuncAttributeMaxDynamicSharedMemorySize, GSM);
    cudaFuncSetAttribute(bf_gemm<0, false, false>, cudaFuncAttributeMaxDynamicSharedMemorySize, GSM);
    cudaFuncSetAttribute(bf_gemm<1, true, true>,   cudaFuncAttributeMaxDynamicSharedMemorySize, GSM);

    const long long sX  = (long long)CC * HWD;    // 512K elts
    const long long sQK = (long long)HWD * 1024;  // 1M elts
    const long long sE  = (long long)HWD * HWD;   // 1M elts
    const float scale = 0.044194173824159216f;    // 512^-0.5

    // 0) weights -> bf16 (+ concat wqk/bqk)
    cvtw_kernel<<<256, 256>>>(wq, wk, wv, wp, bq, bk, wqkb, wvb, wpb, bqk);

    // 1) GroupNorm + transpose -> xnt bf16 [b][i][c]
    groupnorm_t_kernel<<<BB * 32, 256>>>(x, gamma, beta, xnt);

    // 2) QK[i][n] = sum_k xnt[i][k]*wqk[n][k] + bqk[n]   (M=1024, N=1024, K=512)
    {
        dim3 g(1024 / 128, HWD / 256, BB);
        bf_gemm<2, false, false><<<g, 512, GSM>>>(xnt, wqkb, qkb, bqk, nullptr,
            CC, CC, CC, 1024, sX, 0, sQK, 1.f);
    }
    // 3) V[c][j] = sum_k wv[c][k]*xnt[j][k] + bv[c]      (M=512, N=1024, K=512)
    {
        dim3 g(HWD / 128, CC / 256, BB);
        bf_gemm<1, false, false><<<g, 512, GSM>>>(wvb, xnt, vb, bv, nullptr,
            CC, CC, CC, HWD, 0, sX, sX, 1.f);
    }
    // 4) E[i][j] = scale * sum_c Q[i][c]*K[j][c]         (M=1024, N=1024, K=512)
    {
        dim3 g(HWD / 128, HWD / 256, BB);
        bf_gemm<0, false, true><<<g, 512, GSM>>>(qkb, qkb + CC, e, nullptr, nullptr,
            CC, 1024, 1024, HWD, sQK, sQK, sE, scale);
    }
    // 5) softmax rows of E -> attn bf16
    softmax_kernel<<<BB * HWD, 256>>>(e, ab);

    // 6) O[i][c] = sum_j attn[i][j]*V[c][j]              (M=1024, N=512, K=1024)
    {
        dim3 g(CC / 128, HWD / 256, BB);
        bf_gemm<0, false, false><<<g, 512, GSM>>>(ab, vb, ob, nullptr, nullptr,
            HWD, HWD, HWD, CC, sE, sX, sX, 1.f);
    }
    // 7) out[c][i] = sum_k wp[c][k]*O[i][k] + bp[c] + x[c][i]  (M=512, N=1024, K=512)
    {
        dim3 g(HWD / 128, CC / 256, BB);
        bf_gemm<1, true, true><<<g, 512, GSM>>>(wpb, ob, out, bp, x,
            CC, CC, CC, HWD, 0, sX, sX, 1.f);
    }
}